// round 1
// baseline (speedup 1.0000x reference)
#include <cuda_runtime.h>
#include <cuda_bf16.h>
#include <math.h>

// Problem constants (fixed shapes)
#define NN 10000
#define EE 128000
#define CC 128
#define AA 10
#define FF 8
// irreps: l dims 1,3,5 -> 9 components total; mid layout size C*9 = 1152
#define MID 1152
#define OUT_R_OFF 0
#define OUT_I_OFF (NN * MID)          // 11,520,000
#define SC_OFF    (2 * NN * MID)      // 23,040,000

// ---------------- scratch (static device globals; no runtime allocation) ----
__device__ float g_h[NN * CC];              // h = feats @ W_up
__device__ float g_y[NN * CC * AA];         // outer(feats, attrs) flattened u*A+v
__device__ float g_ta[EE * 64];             // mlp ping
__device__ float g_tb[EE * 64];             // mlp pong
__device__ float g_tpw[(size_t)EE * 384];   // per-edge path weights [E][3][128]
__device__ float g_msg[2 * NN * 9 * CC];    // internal msg layout [z][n][jm][c]
__device__ int   g_deg[NN + 8];
__device__ int   g_off[NN + 8];
__device__ int   g_pos[NN + 8];
__device__ int   g_eid[EE];

// ---------------- generic fp32 GEMM ----------------------------------------
// C[r*ldcr + c*ldcc] = act( sum_k A[r*lda + k] * B[k*ldb + c] )
// Block tile 64x64, BK=16, 256 threads, 4x4 per-thread register tile.
#define BM 64
#define BN 64
#define BK 16
__global__ void gemm_k(const float* __restrict__ A, int lda,
                       const float* __restrict__ B, int ldb,
                       float* __restrict__ C, int ldcr, int ldcc,
                       int M, int Nc, int K, int act)
{
    __shared__ float As[BK][BM];
    __shared__ float Bs[BK][BN];
    const int tid = threadIdx.x;           // 0..255
    const int bm = blockIdx.y * BM;
    const int bn = blockIdx.x * BN;
    const int tr = tid >> 4;               // 0..15
    const int tc = tid & 15;               // 0..15

    float acc[4][4];
#pragma unroll
    for (int i = 0; i < 4; i++)
#pragma unroll
        for (int j = 0; j < 4; j++) acc[i][j] = 0.f;

    for (int k0 = 0; k0 < K; k0 += BK) {
        // load A tile (BM x BK)
#pragma unroll 4
        for (int i = tid; i < BM * BK; i += 256) {
            int r = i >> 4;            // /BK
            int c = i & 15;            // %BK
            float v = 0.f;
            int gr = bm + r, gc = k0 + c;
            if (gr < M && gc < K) v = A[(size_t)gr * lda + gc];
            As[c][r] = v;
        }
        // load B tile (BK x BN)
#pragma unroll 4
        for (int i = tid; i < BK * BN; i += 256) {
            int r = i >> 6;            // /BN
            int c = i & 63;            // %BN
            float v = 0.f;
            int gr = k0 + r, gc = bn + c;
            if (gr < K && gc < Nc) v = B[(size_t)gr * ldb + gc];
            Bs[r][c] = v;
        }
        __syncthreads();
#pragma unroll
        for (int kk = 0; kk < BK; kk++) {
            float ar[4], br[4];
#pragma unroll
            for (int i = 0; i < 4; i++) ar[i] = As[kk][tr * 4 + i];
#pragma unroll
            for (int j = 0; j < 4; j++) br[j] = Bs[kk][tc * 4 + j];
#pragma unroll
            for (int i = 0; i < 4; i++)
#pragma unroll
                for (int j = 0; j < 4; j++) acc[i][j] += ar[i] * br[j];
        }
        __syncthreads();
    }

#pragma unroll
    for (int i = 0; i < 4; i++) {
        int r = bm + tr * 4 + i;
        if (r >= M) continue;
#pragma unroll
        for (int j = 0; j < 4; j++) {
            int c = bn + tc * 4 + j;
            if (c >= Nc) continue;
            float v = acc[i][j];
            if (act) v = v / (1.f + __expf(-v));   // silu
            C[(size_t)r * ldcr + (size_t)c * ldcc] = v;
        }
    }
}

// ---------------- y[n, u*A+v] = feats[n,u] * attrs[n,v] ---------------------
__global__ void yprep_k(const float* __restrict__ feats,
                        const float* __restrict__ attrs,
                        float* __restrict__ y)
{
    int n = blockIdx.x;
    __shared__ float sf[CC];
    __shared__ float sa[AA];
    if (threadIdx.x < CC) sf[threadIdx.x] = feats[(size_t)n * CC + threadIdx.x];
    if (threadIdx.x < AA) sa[threadIdx.x] = attrs[(size_t)n * AA + threadIdx.x];
    __syncthreads();
    for (int i = threadIdx.x; i < CC * AA; i += blockDim.x)
        y[(size_t)n * (CC * AA) + i] = sf[i / AA] * sa[i % AA];
}

// ---------------- CSR build -------------------------------------------------
__global__ void zero_deg_k(int* deg, int n)
{
    int i = blockIdx.x * blockDim.x + threadIdx.x;
    if (i < n) deg[i] = 0;
}
__global__ void count_deg_k(const int* __restrict__ recv, int* deg, int e)
{
    int i = blockIdx.x * blockDim.x + threadIdx.x;
    if (i < e) atomicAdd(&deg[recv[i]], 1);
}
__global__ void scan_k(const int* __restrict__ deg, int* off, int* pos, int n)
{
    __shared__ int s[1024];
    int carry = 0;
    for (int base = 0; base < n; base += 1024) {
        int i = base + threadIdx.x;
        int v = (i < n) ? deg[i] : 0;
        s[threadIdx.x] = v;
        __syncthreads();
        for (int st = 1; st < 1024; st <<= 1) {
            int t = 0;
            if ((int)threadIdx.x >= st) t = s[threadIdx.x - st];
            __syncthreads();
            s[threadIdx.x] += t;
            __syncthreads();
        }
        int incl = s[threadIdx.x];
        int excl = incl - v + carry;
        if (i < n) { off[i] = excl; pos[i] = excl; }
        carry += s[1023];
        __syncthreads();
    }
    if (threadIdx.x == 0) off[n] = carry;
}
__global__ void fill_eid_k(const int* __restrict__ recv, int* pos, int* eid, int e)
{
    int i = blockIdx.x * blockDim.x + threadIdx.x;
    if (i < e) {
        int p = atomicAdd(&pos[recv[i]], 1);
        eid[p] = i;
    }
}

// ---------------- gather: TP + segment sum (per receiver node) --------------
// msg[z][n][jm][c] with jm = 0 (l=0), 1..3 (l=1), 4..8 (l=2); jm also indexes
// the 9-component edge SH and the final output m index.
__global__ void gather_k(const float* __restrict__ h,
                         const float* __restrict__ tpw,
                         const float* __restrict__ yr,
                         const float* __restrict__ yi,
                         const int* __restrict__ senders,
                         const int* __restrict__ off,
                         const int* __restrict__ eid,
                         float* __restrict__ msg)
{
    int n = blockIdx.x;
    int c = threadIdx.x;   // 128 threads, one per channel
    float ar[9], ai[9];
#pragma unroll
    for (int j = 0; j < 9; j++) { ar[j] = 0.f; ai[j] = 0.f; }

    int e0 = __ldg(&off[n]);
    int e1 = __ldg(&off[n + 1]);
    for (int p = e0; p < e1; p++) {
        int e = __ldg(&eid[p]);            // broadcast across warp
        int s = __ldg(&senders[e]);
        float hc = h[(size_t)s * CC + c];  // coalesced
        const float* tw = tpw + (size_t)e * 384;
        float xw0 = hc * tw[c];
        float xw1 = hc * tw[128 + c];
        float xw2 = hc * tw[256 + c];
        const float* er = yr + (size_t)e * 9;
        const float* ei = yi + (size_t)e * 9;
        ar[0] += xw0 * __ldg(&er[0]);
        ai[0] += xw0 * __ldg(&ei[0]);
#pragma unroll
        for (int m = 0; m < 3; m++) {
            ar[1 + m] += xw1 * __ldg(&er[1 + m]);
            ai[1 + m] += xw1 * __ldg(&ei[1 + m]);
        }
#pragma unroll
        for (int m = 0; m < 5; m++) {
            ar[4 + m] += xw2 * __ldg(&er[4 + m]);
            ai[4 + m] += xw2 * __ldg(&ei[4 + m]);
        }
    }

    float* mr = msg + (size_t)n * (9 * CC);
    float* mi = msg + (size_t)(NN + n) * (9 * CC);
#pragma unroll
    for (int j = 0; j < 9; j++) {
        mr[j * CC + c] = ar[j];
        mi[j * CC + c] = ai[j];
    }
}

// ---------------- launch ----------------------------------------------------
static inline float* symf(const void* sym)
{
    void* p = nullptr;
    cudaGetSymbolAddress(&p, sym);
    return (float*)p;
}
static inline int* symi(const void* sym)
{
    void* p = nullptr;
    cudaGetSymbolAddress(&p, sym);
    return (int*)p;
}

extern "C" void kernel_launch(void* const* d_in, const int* in_sizes, int n_in,
                              void* d_out, int out_size)
{
    const float* node_attrs = (const float*)d_in[0];
    const float* node_feats = (const float*)d_in[1];
    const float* yr         = (const float*)d_in[2];
    const float* yi         = (const float*)d_in[3];
    const float* edge_feats = (const float*)d_in[4];
    const int*   edge_index = (const int*)d_in[5];
    const float* W_up   = (const float*)d_in[6];
    const float* W_skip = (const float*)d_in[7];
    const float* W1     = (const float*)d_in[8];
    const float* W2     = (const float*)d_in[9];
    const float* W3     = (const float*)d_in[10];
    const float* W4     = (const float*)d_in[11];
    const float* Wl[3]  = { (const float*)d_in[12], (const float*)d_in[13],
                            (const float*)d_in[14] };
    float* out = (float*)d_out;

    float* hh  = symf(g_h);
    float* yy  = symf(g_y);
    float* ta  = symf(g_ta);
    float* tb  = symf(g_tb);
    float* tpw = symf(g_tpw);
    float* msg = symf(g_msg);
    int* deg = symi(g_deg);
    int* off = symi(g_off);
    int* pos = symi(g_pos);
    int* eid = symi(g_eid);

    const int* recv = edge_index + EE;   // edge_index[1]
    const int* send = edge_index;        // edge_index[0]

    dim3 gN128(2, (NN + BM - 1) / BM);      // Nc=128 GEMM on N rows
    dim3 gE64(1, (EE + BM - 1) / BM);       // Nc=64  GEMM on E rows
    dim3 gE384(6, (EE + BM - 1) / BM);      // Nc=384 GEMM on E rows

    // h = node_feats @ W_up
    gemm_k<<<gN128, 256>>>(node_feats, CC, W_up, CC, hh, CC, 1, NN, CC, CC, 0);
    // skip connection: y = outer(feats, attrs); sc = y @ W_skip
    yprep_k<<<NN, 256>>>(node_feats, node_attrs, yy);
    gemm_k<<<gN128, 256>>>(yy, CC * AA, W_skip, CC, out + SC_OFF, CC, 1,
                           NN, CC, CC * AA, 0);
    // edge MLP
    gemm_k<<<gE64, 256>>>(edge_feats, FF, W1, 64, ta, 64, 1, EE, 64, FF, 1);
    gemm_k<<<gE64, 256>>>(ta, 64, W2, 64, tb, 64, 1, EE, 64, 64, 1);
    gemm_k<<<gE64, 256>>>(tb, 64, W3, 64, ta, 64, 1, EE, 64, 64, 1);
    gemm_k<<<gE384, 256>>>(ta, 64, W4, 384, tpw, 384, 1, EE, 384, 64, 0);
    // receiver CSR
    zero_deg_k<<<(NN + 255) / 256, 256>>>(deg, NN);
    count_deg_k<<<(EE + 255) / 256, 256>>>(recv, deg, EE);
    scan_k<<<1, 1024>>>(deg, off, pos, NN);
    fill_eid_k<<<(EE + 255) / 256, 256>>>(recv, pos, eid, EE);
    // tensor product + segment sum
    gather_k<<<NN, 128>>>(hh, tpw, yr, yi, send, off, eid, msg);
    // per-(l,m) channel-mixing linears, writing straight into [n,k,9] layout
    static const int jmbase[3] = {0, 1, 4};
    static const int ldim[3] = {1, 3, 5};
    for (int z = 0; z < 2; z++) {
        for (int l = 0; l < 3; l++) {
            for (int m = 0; m < ldim[l]; m++) {
                int jm = jmbase[l] + m;
                const float* Am = msg + (size_t)z * NN * MID + (size_t)jm * CC;
                float* Cm = out + (size_t)z * NN * MID + jm;
                gemm_k<<<gN128, 256>>>(Am, MID, Wl[l], CC, Cm, MID, 9,
                                       NN, CC, CC, 0);
            }
        }
    }
}

// round 5
// speedup vs baseline: 1.4537x; 1.4537x over previous
#include <cuda_runtime.h>
#include <cuda_bf16.h>
#include <math.h>

// Problem constants (fixed shapes)
#define NN 10000
#define EE 128000
#define CC 128
#define AA 10
#define FF 8
#define MID 1152                       // C * 9
#define SC_OFF (2 * NN * MID)

// msg internal layout per z: [ l0: N*1*C | l1: N*3*C | l2: N*5*C ]
#define ZSZ   (NN * 9 * CC)
#define L0OFF 0
#define L1OFF (NN * CC)
#define L2OFF (4 * NN * CC)

// ---------------- scratch (static device globals) ---------------------------
__device__ float g_h[NN * CC];
__device__ float g_y[NN * CC * AA];
__device__ float g_ta[EE * 64];
__device__ float g_tb[EE * 64];
__device__ float g_tpw[(size_t)EE * 384];
__device__ float g_msg[2 * ZSZ];
__device__ int   g_deg[NN + 8];
__device__ int   g_off[NN + 8];
__device__ int   g_pos[NN + 8];
__device__ int   g_eid[EE];

// ---------------- fp32 GEMM: 128x64 block tile, 8x4 per-thread --------------
// C = act( A[MxK] @ B[KxNcols] ), row-major A (lda), B (ldb).
// Output: if irr_d>0: addr = (r/irr_d)*1152 + c*9 + irr_base + (r%irr_d)
//         else:       addr = r*ldcr + c
#define BM 128
#define BN 64
#define BK 16
#define APAD 132   // 128 + 4
#define BPAD 68    // 64 + 4

__global__ __launch_bounds__(256, 4)
void gemm_k(const float* __restrict__ A, int lda,
            const float* __restrict__ B, int ldb,
            float* __restrict__ C, int ldcr,
            int M, int Ncols, int K, int act, int irr_d, int irr_base)
{
    __shared__ float As[BK * APAD];
    __shared__ float Bs[BK * BPAD];

    const int tid = threadIdx.x;        // 0..255
    const int ty = tid >> 4;            // 0..15 -> 8 rows each
    const int tx = tid & 15;            // 0..15 -> 4 cols each
    const int bm = blockIdx.y * BM;
    const int bn = blockIdx.x * BN;

    float acc[8][4];
#pragma unroll
    for (int i = 0; i < 8; i++)
#pragma unroll
        for (int j = 0; j < 4; j++) acc[i][j] = 0.f;

    for (int k0 = 0; k0 < K; k0 += BK) {
        // ---- load A tile: BM x BK (transpose into As[k][r]) ----
#pragma unroll
        for (int li = 0; li < 2; li++) {
            int idx = tid + li * 256;       // 0..511 float4 slots
            int r = idx >> 2;               // 0..127
            int q = idx & 3;                // float4 within BK
            int gr = bm + r;
            int gk = k0 + q * 4;
            float4 v = make_float4(0.f, 0.f, 0.f, 0.f);
            if (gr < M) {
                if (gk + 4 <= K) {
                    v = *(const float4*)(A + (size_t)gr * lda + gk);
                } else if (gk < K) {
                    const float* ap = A + (size_t)gr * lda + gk;
                    int rem = K - gk;
                    v.x = ap[0];
                    if (rem > 1) v.y = ap[1];
                    if (rem > 2) v.z = ap[2];
                }
            }
            As[(q * 4 + 0) * APAD + r] = v.x;
            As[(q * 4 + 1) * APAD + r] = v.y;
            As[(q * 4 + 2) * APAD + r] = v.z;
            As[(q * 4 + 3) * APAD + r] = v.w;
        }
        // ---- load B tile: BK x BN ----
        {
            int r = tid >> 4;               // 0..15
            int q = tid & 15;               // float4 col
            int gk = k0 + r;
            float4 v = make_float4(0.f, 0.f, 0.f, 0.f);
            if (gk < K) {
                int gc = bn + q * 4;
                if (gc < Ncols)
                    v = *(const float4*)(B + (size_t)gk * ldb + gc);
            }
            *(float4*)&Bs[r * BPAD + q * 4] = v;
        }
        __syncthreads();

#pragma unroll
        for (int kk = 0; kk < BK; kk++) {
            float4 a0 = *(const float4*)&As[kk * APAD + ty * 8];
            float4 a1 = *(const float4*)&As[kk * APAD + ty * 8 + 4];
            float4 b0 = *(const float4*)&Bs[kk * BPAD + tx * 4];
            float ar[8] = {a0.x, a0.y, a0.z, a0.w, a1.x, a1.y, a1.z, a1.w};
            float br[4] = {b0.x, b0.y, b0.z, b0.w};
#pragma unroll
            for (int i = 0; i < 8; i++)
#pragma unroll
                for (int j = 0; j < 4; j++)
                    acc[i][j] = fmaf(ar[i], br[j], acc[i][j]);
        }
        __syncthreads();
    }

    // ---- epilogue ----
#pragma unroll
    for (int i = 0; i < 8; i++) {
        int r = bm + ty * 8 + i;
        if (r >= M) continue;
        size_t rowaddr;
        if (irr_d > 0) {
            int n = r / irr_d;
            int m = r - n * irr_d;
            rowaddr = (size_t)n * MID + irr_base + m;   // + c*9 below
        } else {
            rowaddr = (size_t)r * ldcr;
        }
#pragma unroll
        for (int j = 0; j < 4; j++) {
            int c = bn + tx * 4 + j;
            if (c >= Ncols) continue;
            float v = acc[i][j];
            if (act) v = v / (1.f + __expf(-v));
            size_t addr = irr_d > 0 ? rowaddr + (size_t)c * 9 : rowaddr + c;
            C[addr] = v;
        }
    }
}

// ---------------- y[n, u*A+v] = feats[n,u] * attrs[n,v] ---------------------
__global__ void yprep_k(const float* __restrict__ feats,
                        const float* __restrict__ attrs,
                        float* __restrict__ y)
{
    int n = blockIdx.x;
    __shared__ float sf[CC];
    __shared__ float sa[AA];
    if (threadIdx.x < CC) sf[threadIdx.x] = feats[(size_t)n * CC + threadIdx.x];
    if (threadIdx.x < AA) sa[threadIdx.x] = attrs[(size_t)n * AA + threadIdx.x];
    __syncthreads();
    for (int i = threadIdx.x; i < CC * AA; i += blockDim.x)
        y[(size_t)n * (CC * AA) + i] = sf[i / AA] * sa[i % AA];
}

// ---------------- CSR build -------------------------------------------------
__global__ void zero_deg_k(int* deg, int n)
{
    int i = blockIdx.x * blockDim.x + threadIdx.x;
    if (i < n) deg[i] = 0;
}
__global__ void count_deg_k(const int* __restrict__ recv, int* deg, int e)
{
    int i = blockIdx.x * blockDim.x + threadIdx.x;
    if (i < e) atomicAdd(&deg[recv[i]], 1);
}
__global__ void scan_k(const int* __restrict__ deg, int* off, int* pos, int n)
{
    __shared__ int s[1024];
    int carry = 0;
    for (int base = 0; base < n; base += 1024) {
        int i = base + threadIdx.x;
        int v = (i < n) ? deg[i] : 0;
        s[threadIdx.x] = v;
        __syncthreads();
        for (int st = 1; st < 1024; st <<= 1) {
            int t = 0;
            if ((int)threadIdx.x >= st) t = s[threadIdx.x - st];
            __syncthreads();
            s[threadIdx.x] += t;
            __syncthreads();
        }
        int incl = s[threadIdx.x];
        int excl = incl - v + carry;
        if (i < n) { off[i] = excl; pos[i] = excl; }
        carry += s[1023];
        __syncthreads();
    }
    if (threadIdx.x == 0) off[n] = carry;
}
__global__ void fill_eid_k(const int* __restrict__ recv, int* pos, int* eid, int e)
{
    int i = blockIdx.x * blockDim.x + threadIdx.x;
    if (i < e) {
        int p = atomicAdd(&pos[recv[i]], 1);
        eid[p] = i;
    }
}

// ---------------- gather: TP + segment sum (per receiver node) --------------
// Writes msg in per-l contiguous layout for the fused irreps GEMMs.
__global__ void gather_k(const float* __restrict__ h,
                         const float* __restrict__ tpw,
                         const float* __restrict__ yr,
                         const float* __restrict__ yi,
                         const int* __restrict__ senders,
                         const int* __restrict__ off,
                         const int* __restrict__ eid,
                         float* __restrict__ msg)
{
    int n = blockIdx.x;
    int c = threadIdx.x;   // 128 threads, one per channel
    float ar[9], ai[9];
#pragma unroll
    for (int j = 0; j < 9; j++) { ar[j] = 0.f; ai[j] = 0.f; }

    int e0 = __ldg(&off[n]);
    int e1 = __ldg(&off[n + 1]);
    for (int p = e0; p < e1; p++) {
        int e = __ldg(&eid[p]);
        int s = __ldg(&senders[e]);
        float hc = h[(size_t)s * CC + c];
        const float* tw = tpw + (size_t)e * 384;
        float xw0 = hc * tw[c];
        float xw1 = hc * tw[128 + c];
        float xw2 = hc * tw[256 + c];
        const float* er = yr + (size_t)e * 9;
        const float* ei = yi + (size_t)e * 9;
        ar[0] += xw0 * __ldg(&er[0]);
        ai[0] += xw0 * __ldg(&ei[0]);
#pragma unroll
        for (int m = 0; m < 3; m++) {
            ar[1 + m] += xw1 * __ldg(&er[1 + m]);
            ai[1 + m] += xw1 * __ldg(&ei[1 + m]);
        }
#pragma unroll
        for (int m = 0; m < 5; m++) {
            ar[4 + m] += xw2 * __ldg(&er[4 + m]);
            ai[4 + m] += xw2 * __ldg(&ei[4 + m]);
        }
    }

    // per-l contiguous layout: row (n,m) of block l at loff + (n*d + m)*C
    float* mzr = msg;
    float* mzi = msg + ZSZ;
    mzr[L0OFF + (size_t)n * CC + c] = ar[0];
    mzi[L0OFF + (size_t)n * CC + c] = ai[0];
#pragma unroll
    for (int m = 0; m < 3; m++) {
        mzr[L1OFF + ((size_t)n * 3 + m) * CC + c] = ar[1 + m];
        mzi[L1OFF + ((size_t)n * 3 + m) * CC + c] = ai[1 + m];
    }
#pragma unroll
    for (int m = 0; m < 5; m++) {
        mzr[L2OFF + ((size_t)n * 5 + m) * CC + c] = ar[4 + m];
        mzi[L2OFF + ((size_t)n * 5 + m) * CC + c] = ai[4 + m];
    }
}

// ---------------- launch ----------------------------------------------------
static inline float* symf(const void* sym)
{
    void* p = nullptr;
    cudaGetSymbolAddress(&p, sym);
    return (float*)p;
}
static inline int* symi(const void* sym)
{
    void* p = nullptr;
    cudaGetSymbolAddress(&p, sym);
    return (int*)p;
}

static inline dim3 ggrid(int M, int Ncols)
{
    return dim3((Ncols + BN - 1) / BN, (M + BM - 1) / BM);
}

extern "C" void kernel_launch(void* const* d_in, const int* in_sizes, int n_in,
                              void* d_out, int out_size)
{
    const float* node_attrs = (const float*)d_in[0];
    const float* node_feats = (const float*)d_in[1];
    const float* yr         = (const float*)d_in[2];
    const float* yi         = (const float*)d_in[3];
    const float* edge_feats = (const float*)d_in[4];
    const int*   edge_index = (const int*)d_in[5];
    const float* W_up   = (const float*)d_in[6];
    const float* W_skip = (const float*)d_in[7];
    const float* W1     = (const float*)d_in[8];
    const float* W2     = (const float*)d_in[9];
    const float* W3     = (const float*)d_in[10];
    const float* W4     = (const float*)d_in[11];
    const float* Wl[3]  = { (const float*)d_in[12], (const float*)d_in[13],
                            (const float*)d_in[14] };
    float* out = (float*)d_out;

    float* hh  = symf(g_h);
    float* yy  = symf(g_y);
    float* ta  = symf(g_ta);
    float* tb  = symf(g_tb);
    float* tpw = symf(g_tpw);
    float* msg = symf(g_msg);
    int* deg = symi(g_deg);
    int* off = symi(g_off);
    int* pos = symi(g_pos);
    int* eid = symi(g_eid);

    const int* recv = edge_index + EE;
    const int* send = edge_index;

    // h = node_feats @ W_up
    gemm_k<<<ggrid(NN, CC), 256>>>(node_feats, CC, W_up, CC, hh, CC,
                                   NN, CC, CC, 0, 0, 0);
    // skip: y = outer(feats, attrs); sc = y @ W_skip
    yprep_k<<<NN, 256>>>(node_feats, node_attrs, yy);
    gemm_k<<<ggrid(NN, CC), 256>>>(yy, CC * AA, W_skip, CC, out + SC_OFF, CC,
                                   NN, CC, CC * AA, 0, 0, 0);
    // edge MLP
    gemm_k<<<ggrid(EE, 64), 256>>>(edge_feats, FF, W1, 64, ta, 64,
                                   EE, 64, FF, 1, 0, 0);
    gemm_k<<<ggrid(EE, 64), 256>>>(ta, 64, W2, 64, tb, 64,
                                   EE, 64, 64, 1, 0, 0);
    gemm_k<<<ggrid(EE, 64), 256>>>(tb, 64, W3, 64, ta, 64,
                                   EE, 64, 64, 1, 0, 0);
    gemm_k<<<ggrid(EE, 384), 256>>>(ta, 64, W4, 384, tpw, 384,
                                    EE, 384, 64, 0, 0, 0);
    // receiver CSR
    zero_deg_k<<<(NN + 255) / 256, 256>>>(deg, NN);
    count_deg_k<<<(EE + 255) / 256, 256>>>(recv, deg, EE);
    scan_k<<<1, 1024>>>(deg, off, pos, NN);
    fill_eid_k<<<(EE + 255) / 256, 256>>>(recv, pos, eid, EE);
    // tensor product + segment sum
    gather_k<<<NN, 128>>>(hh, tpw, yr, yi, send, off, eid, msg);
    // fused per-l channel-mixing linears (6 GEMMs instead of 18)
    static const int jmbase[3] = {0, 1, 4};
    static const int ldim[3]   = {1, 3, 5};
    static const int loff[3]   = {L0OFF, L1OFF, L2OFF};
    for (int z = 0; z < 2; z++) {
        for (int l = 0; l < 3; l++) {
            int d = ldim[l];
            const float* Am = msg + (size_t)z * ZSZ + loff[l];
            float* Cm = out + (size_t)z * NN * MID;
            gemm_k<<<ggrid(NN * d, CC), 256>>>(Am, CC, Wl[l], CC, Cm, 0,
                                               NN * d, CC, CC, 0, d, jmbase[l]);
        }
    }
}

// round 7
// speedup vs baseline: 1.7066x; 1.1740x over previous
#include <cuda_runtime.h>
#include <cuda_bf16.h>
#include <math.h>
#include <stdint.h>

// Problem constants (fixed shapes)
#define NN 10000
#define EE 128000
#define CC 128
#define AA 10
#define FF 8
#define MID 1152                       // C * 9
#define SC_OFF (2 * NN * MID)

// msg internal layout per z: [ l0: N*1*C | l1: N*3*C | l2: N*5*C ]
#define ZSZ   (NN * 9 * CC)
#define L0OFF 0
#define L1OFF (NN * CC)
#define L2OFF (4 * NN * CC)

// ---------------- scratch (static device globals) ---------------------------
__device__ __align__(128) float g_h[NN * CC];
__device__ __align__(128) float g_y[NN * CC * AA];
__device__ __align__(128) float g_ta[EE * 64];
__device__ __align__(128) float g_tb[EE * 64];
__device__ __align__(128) float g_tpw[(size_t)EE * 384];
__device__ __align__(128) float g_msg[2 * ZSZ];
__device__ __align__(128) float g_wt[262656];    // transposed weights, fp32
__device__ int   g_deg[NN + 8];
__device__ int   g_off[NN + 8];
__device__ int   g_pos[NN + 8];
__device__ int   g_eid[EE];

// transposed-weight offsets inside g_wt
#define WUP_T 0
#define WSK_T 16384
#define W1_T  180224
#define W2_T  180736
#define W3_T  184832
#define W4_T  188928
#define WL0_T 213504
#define WL1_T 229888
#define WL2_T 246272

// ---------------- helpers ---------------------------------------------------
__device__ __forceinline__ uint32_t smem_to_u32(const void* p) {
    uint32_t a;
    asm("{ .reg .u64 t; cvta.to.shared.u64 t, %1; cvt.u32.u64 %0, t; }"
        : "=r"(a) : "l"(p));
    return a;
}

__device__ __forceinline__ void ldm_x4(uint32_t addr, uint32_t* r) {
    asm volatile("ldmatrix.sync.aligned.m8n8.x4.shared.b16 {%0,%1,%2,%3}, [%4];"
                 : "=r"(r[0]), "=r"(r[1]), "=r"(r[2]), "=r"(r[3]) : "r"(addr));
}

__device__ __forceinline__ void mma16816(float* d, const uint32_t* a,
                                         const uint32_t* b) {
    asm volatile("mma.sync.aligned.m16n8k16.row.col.f32.bf16.bf16.f32 "
                 "{%0,%1,%2,%3}, {%4,%5,%6,%7}, {%8,%9}, {%0,%1,%2,%3};"
                 : "+f"(d[0]), "+f"(d[1]), "+f"(d[2]), "+f"(d[3])
                 : "r"(a[0]), "r"(a[1]), "r"(a[2]), "r"(a[3]),
                   "r"(b[0]), "r"(b[1]));
}

// split fp32x4 -> bf16 hi/lo packed pairs
__device__ __forceinline__ void split4(float4 v, uint2& hi, uint2& lo)
{
    __nv_bfloat162 h01 = __floats2bfloat162_rn(v.x, v.y);
    __nv_bfloat162 h23 = __floats2bfloat162_rn(v.z, v.w);
    float2 f01 = __bfloat1622float2(h01);
    float2 f23 = __bfloat1622float2(h23);
    __nv_bfloat162 l01 = __floats2bfloat162_rn(v.x - f01.x, v.y - f01.y);
    __nv_bfloat162 l23 = __floats2bfloat162_rn(v.z - f23.x, v.w - f23.y);
    hi.x = *reinterpret_cast<uint32_t*>(&h01);
    hi.y = *reinterpret_cast<uint32_t*>(&h23);
    lo.x = *reinterpret_cast<uint32_t*>(&l01);
    lo.y = *reinterpret_cast<uint32_t*>(&l23);
}

// ---------------- mma.sync bf16 split GEMM ----------------------------------
// C = act( A[MxK] @ Bt[Ncols x K]^T ), fp32 in/out.
// Block tile 128x64, K-chunk 64, 8 warps (4m x 2n), warp tile 32x32.
// Smem rows: 72 bf16 = 144 B (ldmatrix conflict-free: 36 banks stride).
// Output: if irr_d>0: addr = (r/irr_d)*MID + irr_base + (r%irr_d) + c*9
//         else:       addr = r*ldcr + c
#define ROWB 144
#define S_AH 0
#define S_AL (128 * ROWB)
#define S_BH (2 * 128 * ROWB)
#define S_BL (2 * 128 * ROWB + 64 * ROWB)
#define S_TOT (2 * 128 * ROWB + 2 * 64 * ROWB)   // 55296 bytes

__global__ __launch_bounds__(256)
void tc_gemm_k(const float* __restrict__ A, int lda,
               const float* __restrict__ Bt,
               float* __restrict__ C, int ldcr,
               int M, int K, int act, int irr_d, int irr_base)
{
    extern __shared__ char smem[];
    const uint32_t sb = smem_to_u32(smem);
    const int tid = threadIdx.x;
    const int lane = tid & 31;
    const int wid = tid >> 5;
    const int wm = (wid & 3) * 32;      // warp m offset in block
    const int wn = (wid >> 2) * 32;     // warp n offset in block
    const int bm = blockIdx.y * 128;
    const int bn = blockIdx.x * 64;

    float acc[2][4][4];
#pragma unroll
    for (int i = 0; i < 2; i++)
#pragma unroll
        for (int j = 0; j < 4; j++)
#pragma unroll
            for (int q = 0; q < 4; q++) acc[i][j][q] = 0.f;

    // ldmatrix per-lane address offsets (bytes, within each tile region)
    const uint32_t aRow = wm + (lane & 15);
    const uint32_t aKp = (lane >> 4) * 8;
    const uint32_t aOff0 = aRow * ROWB + aKp * 2;
    const uint32_t aOff1 = (aRow + 16) * ROWB + aKp * 2;
    const uint32_t bRow = (lane & 7) + ((lane >> 4) * 8);
    const uint32_t bKp = ((lane >> 3) & 1) * 8;
    const uint32_t bOff0 = (wn + bRow) * ROWB + bKp * 2;
    const uint32_t bOff1 = (wn + 16 + bRow) * ROWB + bKp * 2;

    const int nchunks = (K + 63) >> 6;
    for (int ch = 0; ch < nchunks; ch++) {
        const int k0 = ch << 6;
        // ---- stage A tile: 128 x 64 fp32 -> bf16 hi/lo ----
#pragma unroll
        for (int li = 0; li < 8; li++) {
            int slot = tid + li * 256;          // 0..2047
            int r = slot >> 4;
            int c4 = slot & 15;
            int gr = bm + r, gk = k0 + c4 * 4;
            float4 v = make_float4(0.f, 0.f, 0.f, 0.f);
            if (gr < M && gk < K) {
                if (gk + 4 <= K) {
                    v = *(const float4*)(A + (size_t)gr * lda + gk);
                } else {
                    const float* p = A + (size_t)gr * lda + gk;
                    int rem = K - gk;
                    v.x = p[0];
                    if (rem > 1) v.y = p[1];
                    if (rem > 2) v.z = p[2];
                }
            }
            uint2 hi, lo;
            split4(v, hi, lo);
            uint32_t off = (uint32_t)(r * ROWB + c4 * 8);
            *(uint2*)(smem + S_AH + off) = hi;
            *(uint2*)(smem + S_AL + off) = lo;
        }
        // ---- stage B tile: 64 x 64 ----
#pragma unroll
        for (int li = 0; li < 4; li++) {
            int slot = tid + li * 256;          // 0..1023
            int r = slot >> 4;
            int c4 = slot & 15;
            int gk = k0 + c4 * 4;
            float4 v = make_float4(0.f, 0.f, 0.f, 0.f);
            if (gk < K) {
                if (gk + 4 <= K) {
                    v = *(const float4*)(Bt + (size_t)(bn + r) * K + gk);
                } else {
                    const float* p = Bt + (size_t)(bn + r) * K + gk;
                    int rem = K - gk;
                    v.x = p[0];
                    if (rem > 1) v.y = p[1];
                    if (rem > 2) v.z = p[2];
                }
            }
            uint2 hi, lo;
            split4(v, hi, lo);
            uint32_t off = (uint32_t)(r * ROWB + c4 * 8);
            *(uint2*)(smem + S_BH + off) = hi;
            *(uint2*)(smem + S_BL + off) = lo;
        }
        __syncthreads();

        // ---- 4 k16 steps, 3 split passes each ----
#pragma unroll
        for (int ks = 0; ks < 4; ks++) {
            const uint32_t k2 = (uint32_t)(ks * 32);   // 16 bf16 = 32 bytes
            uint32_t a0[4], a1[4], b0[4], b1[4], bl0[4], bl1[4];
            ldm_x4(sb + S_AH + aOff0 + k2, a0);
            ldm_x4(sb + S_AH + aOff1 + k2, a1);
            ldm_x4(sb + S_BH + bOff0 + k2, b0);
            ldm_x4(sb + S_BH + bOff1 + k2, b1);
            // hi * hi
            mma16816(acc[0][0], a0, b0 + 0);
            mma16816(acc[0][1], a0, b0 + 2);
            mma16816(acc[0][2], a0, b1 + 0);
            mma16816(acc[0][3], a0, b1 + 2);
            mma16816(acc[1][0], a1, b0 + 0);
            mma16816(acc[1][1], a1, b0 + 2);
            mma16816(acc[1][2], a1, b1 + 0);
            mma16816(acc[1][3], a1, b1 + 2);
            // hi * lo
            ldm_x4(sb + S_BL + bOff0 + k2, bl0);
            ldm_x4(sb + S_BL + bOff1 + k2, bl1);
            mma16816(acc[0][0], a0, bl0 + 0);
            mma16816(acc[0][1], a0, bl0 + 2);
            mma16816(acc[0][2], a0, bl1 + 0);
            mma16816(acc[0][3], a0, bl1 + 2);
            mma16816(acc[1][0], a1, bl0 + 0);
            mma16816(acc[1][1], a1, bl0 + 2);
            mma16816(acc[1][2], a1, bl1 + 0);
            mma16816(acc[1][3], a1, bl1 + 2);
            // lo * hi (reuse a regs)
            ldm_x4(sb + S_AL + aOff0 + k2, a0);
            ldm_x4(sb + S_AL + aOff1 + k2, a1);
            mma16816(acc[0][0], a0, b0 + 0);
            mma16816(acc[0][1], a0, b0 + 2);
            mma16816(acc[0][2], a0, b1 + 0);
            mma16816(acc[0][3], a0, b1 + 2);
            mma16816(acc[1][0], a1, b0 + 0);
            mma16816(acc[1][1], a1, b0 + 2);
            mma16816(acc[1][2], a1, b1 + 0);
            mma16816(acc[1][3], a1, b1 + 2);
        }
        __syncthreads();
    }

    // ---- epilogue ----
#pragma unroll
    for (int mt = 0; mt < 2; mt++) {
        int r0g = bm + wm + mt * 16 + (lane >> 2);
#pragma unroll
        for (int nt = 0; nt < 4; nt++) {
            int cg = bn + wn + nt * 8 + (lane & 3) * 2;
            float* d = acc[mt][nt];
#pragma unroll
            for (int half = 0; half < 2; half++) {
                int r = r0g + half * 8;
                if (r >= M) continue;
                float v0 = d[half * 2 + 0];
                float v1 = d[half * 2 + 1];
                if (act) {
                    v0 = v0 / (1.f + __expf(-v0));
                    v1 = v1 / (1.f + __expf(-v1));
                }
                if (irr_d > 0) {
                    int n = r / irr_d;
                    int m = r - n * irr_d;
                    size_t base = (size_t)n * MID + irr_base + m;
                    C[base + (size_t)cg * 9] = v0;
                    C[base + (size_t)(cg + 1) * 9] = v1;
                } else {
                    size_t base = (size_t)r * ldcr + cg;
                    C[base] = v0;
                    C[base + 1] = v1;
                }
            }
        }
    }
}

// ---------------- weight transpose: out[N][K] = in[K][N] --------------------
__global__ void transpose_k(const float* __restrict__ in, float* __restrict__ out,
                            int K, int N)
{
    int i = blockIdx.x * blockDim.x + threadIdx.x;
    if (i < K * N) {
        int k = i / N, c = i - k * N;
        out[(size_t)c * K + k] = in[i];
    }
}

// ---------------- y[n, u*A+v] = feats[n,u] * attrs[n,v] ---------------------
__global__ void yprep_k(const float* __restrict__ feats,
                        const float* __restrict__ attrs,
                        float* __restrict__ y)
{
    int n = blockIdx.x;
    __shared__ float sf[CC];
    __shared__ float sa[AA];
    if (threadIdx.x < CC) sf[threadIdx.x] = feats[(size_t)n * CC + threadIdx.x];
    if (threadIdx.x < AA) sa[threadIdx.x] = attrs[(size_t)n * AA + threadIdx.x];
    __syncthreads();
    for (int i = threadIdx.x; i < CC * AA; i += blockDim.x)
        y[(size_t)n * (CC * AA) + i] = sf[i / AA] * sa[i % AA];
}

// ---------------- CSR build -------------------------------------------------
__global__ void zero_deg_k(int* deg, int n)
{
    int i = blockIdx.x * blockDim.x + threadIdx.x;
    if (i < n) deg[i] = 0;
}
__global__ void count_deg_k(const int* __restrict__ recv, int* deg, int e)
{
    int i = blockIdx.x * blockDim.x + threadIdx.x;
    if (i < e) atomicAdd(&deg[recv[i]], 1);
}
__global__ void scan_k(const int* __restrict__ deg, int* off, int* pos, int n)
{
    __shared__ int s[1024];
    int carry = 0;
    for (int base = 0; base < n; base += 1024) {
        int i = base + threadIdx.x;
        int v = (i < n) ? deg[i] : 0;
        s[threadIdx.x] = v;
        __syncthreads();
        for (int st = 1; st < 1024; st <<= 1) {
            int t = 0;
            if ((int)threadIdx.x >= st) t = s[threadIdx.x - st];
            __syncthreads();
            s[threadIdx.x] += t;
            __syncthreads();
        }
        int incl = s[threadIdx.x];
        int excl = incl - v + carry;
        if (i < n) { off[i] = excl; pos[i] = excl; }
        carry += s[1023];
        __syncthreads();
    }
    if (threadIdx.x == 0) off[n] = carry;
}
__global__ void fill_eid_k(const int* __restrict__ recv, int* pos, int* eid, int e)
{
    int i = blockIdx.x * blockDim.x + threadIdx.x;
    if (i < e) {
        int p = atomicAdd(&pos[recv[i]], 1);
        eid[p] = i;
    }
}

// ---------------- gather: TP + segment sum (per receiver node) --------------
__global__ void gather_k(const float* __restrict__ h,
                         const float* __restrict__ tpw,
                         const float* __restrict__ yr,
                         const float* __restrict__ yi,
                         const int* __restrict__ senders,
                         const int* __restrict__ off,
                         const int* __restrict__ eid,
                         float* __restrict__ msg)
{
    int n = blockIdx.x;
    int c = threadIdx.x;   // 128 threads, one per channel
    float ar[9], ai[9];
#pragma unroll
    for (int j = 0; j < 9; j++) { ar[j] = 0.f; ai[j] = 0.f; }

    int e0 = __ldg(&off[n]);
    int e1 = __ldg(&off[n + 1]);
    for (int p = e0; p < e1; p++) {
        int e = __ldg(&eid[p]);
        int s = __ldg(&senders[e]);
        float hc = h[(size_t)s * CC + c];
        const float* tw = tpw + (size_t)e * 384;
        float xw0 = hc * tw[c];
        float xw1 = hc * tw[128 + c];
        float xw2 = hc * tw[256 + c];
        const float* er = yr + (size_t)e * 9;
        const float* ei = yi + (size_t)e * 9;
        ar[0] += xw0 * __ldg(&er[0]);
        ai[0] += xw0 * __ldg(&ei[0]);
#pragma unroll
        for (int m = 0; m < 3; m++) {
            ar[1 + m] += xw1 * __ldg(&er[1 + m]);
            ai[1 + m] += xw1 * __ldg(&ei[1 + m]);
        }
#pragma unroll
        for (int m = 0; m < 5; m++) {
            ar[4 + m] += xw2 * __ldg(&er[4 + m]);
            ai[4 + m] += xw2 * __ldg(&ei[4 + m]);
        }
    }

    float* mzr = msg;
    float* mzi = msg + ZSZ;
    mzr[L0OFF + (size_t)n * CC + c] = ar[0];
    mzi[L0OFF + (size_t)n * CC + c] = ai[0];
#pragma unroll
    for (int m = 0; m < 3; m++) {
        mzr[L1OFF + ((size_t)n * 3 + m) * CC + c] = ar[1 + m];
        mzi[L1OFF + ((size_t)n * 3 + m) * CC + c] = ai[1 + m];
    }
#pragma unroll
    for (int m = 0; m < 5; m++) {
        mzr[L2OFF + ((size_t)n * 5 + m) * CC + c] = ar[4 + m];
        mzi[L2OFF + ((size_t)n * 5 + m) * CC + c] = ai[4 + m];
    }
}

// ---------------- launch ----------------------------------------------------
static inline float* symf(const void* sym)
{
    void* p = nullptr;
    cudaGetSymbolAddress(&p, sym);
    return (float*)p;
}
static inline int* symi(const void* sym)
{
    void* p = nullptr;
    cudaGetSymbolAddress(&p, sym);
    return (int*)p;
}

static inline void tc_gemm(const float* A, int lda, const float* Bt, float* C,
                           int ldcr, int M, int Ncols, int K, int act,
                           int irr_d, int irr_base)
{
    dim3 grid(Ncols / 64, (M + 127) / 128);
    tc_gemm_k<<<grid, 256, S_TOT>>>(A, lda, Bt, C, ldcr, M, K, act,
                                    irr_d, irr_base);
}

extern "C" void kernel_launch(void* const* d_in, const int* in_sizes, int n_in,
                              void* d_out, int out_size)
{
    const float* node_attrs = (const float*)d_in[0];
    const float* node_feats = (const float*)d_in[1];
    const float* yr         = (const float*)d_in[2];
    const float* yi         = (const float*)d_in[3];
    const float* edge_feats = (const float*)d_in[4];
    const int*   edge_index = (const int*)d_in[5];
    const float* W_up   = (const float*)d_in[6];
    const float* W_skip = (const float*)d_in[7];
    const float* W1     = (const float*)d_in[8];
    const float* W2     = (const float*)d_in[9];
    const float* W3     = (const float*)d_in[10];
    const float* W4     = (const float*)d_in[11];
    const float* Wl[3]  = { (const float*)d_in[12], (const float*)d_in[13],
                            (const float*)d_in[14] };
    float* out = (float*)d_out;

    static int smem_set = 0;
    if (!smem_set) {
        cudaFuncSetAttribute(tc_gemm_k,
                             cudaFuncAttributeMaxDynamicSharedMemorySize, S_TOT);
        smem_set = 1;
    }

    float* hh  = symf(g_h);
    float* yy  = symf(g_y);
    float* ta  = symf(g_ta);
    float* tb  = symf(g_tb);
    float* tpw = symf(g_tpw);
    float* msg = symf(g_msg);
    float* wt  = symf(g_wt);
    int* deg = symi(g_deg);
    int* off = symi(g_off);
    int* pos = symi(g_pos);
    int* eid = symi(g_eid);

    const int* recv = edge_index + EE;
    const int* send = edge_index;

    // transpose all weights to [N][K] fp32
    transpose_k<<<(128 * 128 + 255) / 256, 256>>>(W_up, wt + WUP_T, 128, 128);
    transpose_k<<<(1280 * 128 + 255) / 256, 256>>>(W_skip, wt + WSK_T, 1280, 128);
    transpose_k<<<(8 * 64 + 255) / 256, 256>>>(W1, wt + W1_T, 8, 64);
    transpose_k<<<(64 * 64 + 255) / 256, 256>>>(W2, wt + W2_T, 64, 64);
    transpose_k<<<(64 * 64 + 255) / 256, 256>>>(W3, wt + W3_T, 64, 64);
    transpose_k<<<(64 * 384 + 255) / 256, 256>>>(W4, wt + W4_T, 64, 384);
    transpose_k<<<(128 * 128 + 255) / 256, 256>>>(Wl[0], wt + WL0_T, 128, 128);
    transpose_k<<<(128 * 128 + 255) / 256, 256>>>(Wl[1], wt + WL1_T, 128, 128);
    transpose_k<<<(128 * 128 + 255) / 256, 256>>>(Wl[2], wt + WL2_T, 128, 128);

    // h = node_feats @ W_up
    tc_gemm(node_feats, CC, wt + WUP_T, hh, CC, NN, CC, CC, 0, 0, 0);
    // skip: y = outer(feats, attrs); sc = y @ W_skip
    yprep_k<<<NN, 256>>>(node_feats, node_attrs, yy);
    tc_gemm(yy, CC * AA, wt + WSK_T, out + SC_OFF, CC, NN, CC, CC * AA, 0, 0, 0);
    // edge MLP
    tc_gemm(edge_feats, FF, wt + W1_T, ta, 64, EE, 64, FF, 1, 0, 0);
    tc_gemm(ta, 64, wt + W2_T, tb, 64, EE, 64, 64, 1, 0, 0);
    tc_gemm(tb, 64, wt + W3_T, ta, 64, EE, 64, 64, 1, 0, 0);
    tc_gemm(ta, 64, wt + W4_T, tpw, 384, EE, 384, 64, 0, 0, 0);
    // receiver CSR
    zero_deg_k<<<(NN + 255) / 256, 256>>>(deg, NN);
    count_deg_k<<<(EE + 255) / 256, 256>>>(recv, deg, EE);
    scan_k<<<1, 1024>>>(deg, off, pos, NN);
    fill_eid_k<<<(EE + 255) / 256, 256>>>(recv, pos, eid, EE);
    // tensor product + segment sum
    gather_k<<<NN, 128>>>(hh, tpw, yr, yi, send, off, eid, msg);
    // fused per-l channel-mixing linears
    static const int jmbase[3] = {0, 1, 4};
    static const int ldim[3]   = {1, 3, 5};
    static const int loff[3]   = {L0OFF, L1OFF, L2OFF};
    for (int z = 0; z < 2; z++) {
        for (int l = 0; l < 3; l++) {
            int d = ldim[l];
            const float* Am = msg + (size_t)z * ZSZ + loff[l];
            float* Cm = out + (size_t)z * NN * MID;
            tc_gemm(Am, CC, wt + (l == 0 ? WL0_T : l == 1 ? WL1_T : WL2_T),
                    Cm, 0, NN * d, CC, CC, 0, d, jmbase[l]);
        }
    }
}

// round 9
// speedup vs baseline: 1.7626x; 1.0329x over previous
#include <cuda_runtime.h>
#include <cuda_bf16.h>
#include <math.h>
#include <stdint.h>

// Problem constants (fixed shapes)
#define NN 10000
#define EE 128000
#define CC 128
#define AA 10
#define FF 8
#define MID 1152                       // C * 9
#define SC_OFF (2 * NN * MID)

// msg internal layout per z: [ l0: N*1*C | l1: N*3*C | l2: N*5*C ]
#define ZSZ   (NN * 9 * CC)
#define L0OFF 0
#define L1OFF (NN * CC)
#define L2OFF (4 * NN * CC)

// ---------------- scratch (static device globals) ---------------------------
__device__ __align__(128) float g_h[NN * CC];
__device__ __align__(128) float g_y[NN * CC * AA];
__device__ __align__(128) float g_ta[EE * 64];
__device__ __align__(128) float g_tb[EE * 64];
__device__ __align__(128) float g_tpw[(size_t)EE * 384];
__device__ __align__(128) float g_msg[2 * ZSZ];
__device__ __align__(128) float g_tmp[2 * ZSZ];  // irreps GEMM coalesced output
__device__ __align__(128) float g_wt[262656];    // transposed weights, fp32
__device__ int   g_deg[NN + 8];
__device__ int   g_off[NN + 8];
__device__ int   g_pos[NN + 8];
__device__ int   g_eid[EE];

// transposed-weight offsets inside g_wt
#define WUP_T 0
#define WSK_T 16384
#define W1_T  180224
#define W2_T  180736
#define W3_T  184832
#define W4_T  188928
#define WL0_T 213504
#define WL1_T 229888
#define WL2_T 246272

// ---------------- helpers ---------------------------------------------------
__device__ __forceinline__ uint32_t smem_to_u32(const void* p) {
    uint32_t a;
    asm("{ .reg .u64 t; cvta.to.shared.u64 t, %1; cvt.u32.u64 %0, t; }"
        : "=r"(a) : "l"(p));
    return a;
}

__device__ __forceinline__ void ldm_x4(uint32_t addr, uint32_t* r) {
    asm volatile("ldmatrix.sync.aligned.m8n8.x4.shared.b16 {%0,%1,%2,%3}, [%4];"
                 : "=r"(r[0]), "=r"(r[1]), "=r"(r[2]), "=r"(r[3]) : "r"(addr));
}

__device__ __forceinline__ void mma16816(float* d, const uint32_t* a,
                                         const uint32_t* b) {
    asm volatile("mma.sync.aligned.m16n8k16.row.col.f32.bf16.bf16.f32 "
                 "{%0,%1,%2,%3}, {%4,%5,%6,%7}, {%8,%9}, {%0,%1,%2,%3};"
                 : "+f"(d[0]), "+f"(d[1]), "+f"(d[2]), "+f"(d[3])
                 : "r"(a[0]), "r"(a[1]), "r"(a[2]), "r"(a[3]),
                   "r"(b[0]), "r"(b[1]));
}

// split fp32x4 -> bf16 hi/lo packed pairs
__device__ __forceinline__ void split4(float4 v, uint2& hi, uint2& lo)
{
    __nv_bfloat162 h01 = __floats2bfloat162_rn(v.x, v.y);
    __nv_bfloat162 h23 = __floats2bfloat162_rn(v.z, v.w);
    float2 f01 = __bfloat1622float2(h01);
    float2 f23 = __bfloat1622float2(h23);
    __nv_bfloat162 l01 = __floats2bfloat162_rn(v.x - f01.x, v.y - f01.y);
    __nv_bfloat162 l23 = __floats2bfloat162_rn(v.z - f23.x, v.w - f23.y);
    hi.x = *reinterpret_cast<uint32_t*>(&h01);
    hi.y = *reinterpret_cast<uint32_t*>(&h23);
    lo.x = *reinterpret_cast<uint32_t*>(&l01);
    lo.y = *reinterpret_cast<uint32_t*>(&l23);
}

// ---------------- mma.sync bf16 split GEMM ----------------------------------
// C = act( A[MxK] @ Bt[Ncols x K]^T ), fp32 in/out.
// Block tile 128x64, K-chunk 64, 8 warps (4m x 2n), warp tile 32x32.
#define ROWB 144
#define S_AH 0
#define S_AL (128 * ROWB)
#define S_BH (2 * 128 * ROWB)
#define S_BL (2 * 128 * ROWB + 64 * ROWB)
#define S_TOT (2 * 128 * ROWB + 2 * 64 * ROWB)   // 55296 bytes

__global__ __launch_bounds__(256)
void tc_gemm_k(const float* __restrict__ A, int lda,
               const float* __restrict__ Bt,
               float* __restrict__ C, int ldcr,
               int M, int K, int act)
{
    extern __shared__ char smem[];
    const uint32_t sb = smem_to_u32(smem);
    const int tid = threadIdx.x;
    const int lane = tid & 31;
    const int wid = tid >> 5;
    const int wm = (wid & 3) * 32;      // warp m offset in block
    const int wn = (wid >> 2) * 32;     // warp n offset in block
    const int bm = blockIdx.y * 128;
    const int bn = blockIdx.x * 64;

    float acc[2][4][4];
#pragma unroll
    for (int i = 0; i < 2; i++)
#pragma unroll
        for (int j = 0; j < 4; j++)
#pragma unroll
            for (int q = 0; q < 4; q++) acc[i][j][q] = 0.f;

    const uint32_t aRow = wm + (lane & 15);
    const uint32_t aKp = (lane >> 4) * 8;
    const uint32_t aOff0 = aRow * ROWB + aKp * 2;
    const uint32_t aOff1 = (aRow + 16) * ROWB + aKp * 2;
    const uint32_t bRow = (lane & 7) + ((lane >> 4) * 8);
    const uint32_t bKp = ((lane >> 3) & 1) * 8;
    const uint32_t bOff0 = (wn + bRow) * ROWB + bKp * 2;
    const uint32_t bOff1 = (wn + 16 + bRow) * ROWB + bKp * 2;

    const int nchunks = (K + 63) >> 6;
    for (int ch = 0; ch < nchunks; ch++) {
        const int k0 = ch << 6;
        // ---- stage A tile: 128 x 64 fp32 -> bf16 hi/lo ----
#pragma unroll
        for (int li = 0; li < 8; li++) {
            int slot = tid + li * 256;          // 0..2047
            int r = slot >> 4;
            int c4 = slot & 15;
            int gr = bm + r, gk = k0 + c4 * 4;
            float4 v = make_float4(0.f, 0.f, 0.f, 0.f);
            if (gr < M && gk < K) {
                if (gk + 4 <= K) {
                    v = *(const float4*)(A + (size_t)gr * lda + gk);
                } else {
                    const float* p = A + (size_t)gr * lda + gk;
                    int rem = K - gk;
                    v.x = p[0];
                    if (rem > 1) v.y = p[1];
                    if (rem > 2) v.z = p[2];
                }
            }
            uint2 hi, lo;
            split4(v, hi, lo);
            uint32_t off = (uint32_t)(r * ROWB + c4 * 8);
            *(uint2*)(smem + S_AH + off) = hi;
            *(uint2*)(smem + S_AL + off) = lo;
        }
        // ---- stage B tile: 64 x 64 ----
#pragma unroll
        for (int li = 0; li < 4; li++) {
            int slot = tid + li * 256;          // 0..1023
            int r = slot >> 4;
            int c4 = slot & 15;
            int gk = k0 + c4 * 4;
            float4 v = make_float4(0.f, 0.f, 0.f, 0.f);
            if (gk < K) {
                if (gk + 4 <= K) {
                    v = *(const float4*)(Bt + (size_t)(bn + r) * K + gk);
                } else {
                    const float* p = Bt + (size_t)(bn + r) * K + gk;
                    int rem = K - gk;
                    v.x = p[0];
                    if (rem > 1) v.y = p[1];
                    if (rem > 2) v.z = p[2];
                }
            }
            uint2 hi, lo;
            split4(v, hi, lo);
            uint32_t off = (uint32_t)(r * ROWB + c4 * 8);
            *(uint2*)(smem + S_BH + off) = hi;
            *(uint2*)(smem + S_BL + off) = lo;
        }
        __syncthreads();

#pragma unroll
        for (int ks = 0; ks < 4; ks++) {
            const uint32_t k2 = (uint32_t)(ks * 32);
            uint32_t a0[4], a1[4], b0[4], b1[4], bl0[4], bl1[4];
            ldm_x4(sb + S_AH + aOff0 + k2, a0);
            ldm_x4(sb + S_AH + aOff1 + k2, a1);
            ldm_x4(sb + S_BH + bOff0 + k2, b0);
            ldm_x4(sb + S_BH + bOff1 + k2, b1);
            mma16816(acc[0][0], a0, b0 + 0);
            mma16816(acc[0][1], a0, b0 + 2);
            mma16816(acc[0][2], a0, b1 + 0);
            mma16816(acc[0][3], a0, b1 + 2);
            mma16816(acc[1][0], a1, b0 + 0);
            mma16816(acc[1][1], a1, b0 + 2);
            mma16816(acc[1][2], a1, b1 + 0);
            mma16816(acc[1][3], a1, b1 + 2);
            ldm_x4(sb + S_BL + bOff0 + k2, bl0);
            ldm_x4(sb + S_BL + bOff1 + k2, bl1);
            mma16816(acc[0][0], a0, bl0 + 0);
            mma16816(acc[0][1], a0, bl0 + 2);
            mma16816(acc[0][2], a0, bl1 + 0);
            mma16816(acc[0][3], a0, bl1 + 2);
            mma16816(acc[1][0], a1, bl0 + 0);
            mma16816(acc[1][1], a1, bl0 + 2);
            mma16816(acc[1][2], a1, bl1 + 0);
            mma16816(acc[1][3], a1, bl1 + 2);
            ldm_x4(sb + S_AL + aOff0 + k2, a0);
            ldm_x4(sb + S_AL + aOff1 + k2, a1);
            mma16816(acc[0][0], a0, b0 + 0);
            mma16816(acc[0][1], a0, b0 + 2);
            mma16816(acc[0][2], a0, b1 + 0);
            mma16816(acc[0][3], a0, b1 + 2);
            mma16816(acc[1][0], a1, b0 + 0);
            mma16816(acc[1][1], a1, b0 + 2);
            mma16816(acc[1][2], a1, b1 + 0);
            mma16816(acc[1][3], a1, b1 + 2);
        }
        __syncthreads();
    }

    // ---- epilogue (row-major C, ldcr stride) ----
#pragma unroll
    for (int mt = 0; mt < 2; mt++) {
        int r0g = bm + wm + mt * 16 + (lane >> 2);
#pragma unroll
        for (int nt = 0; nt < 4; nt++) {
            int cg = bn + wn + nt * 8 + (lane & 3) * 2;
            float* d = acc[mt][nt];
#pragma unroll
            for (int half = 0; half < 2; half++) {
                int r = r0g + half * 8;
                if (r >= M) continue;
                float v0 = d[half * 2 + 0];
                float v1 = d[half * 2 + 1];
                if (act) {
                    v0 = v0 / (1.f + __expf(-v0));
                    v1 = v1 / (1.f + __expf(-v1));
                }
                size_t base = (size_t)r * ldcr + cg;
                C[base] = v0;
                C[base + 1] = v1;
            }
        }
    }
}

// ---------------- fused weight transpose ------------------------------------
// 9 segments, each out[c*K + k] = in[k*N + c].
#define TSEG 9
__global__ void transpose_all_k(const float* __restrict__ s0, const float* __restrict__ s1,
                                const float* __restrict__ s2, const float* __restrict__ s3,
                                const float* __restrict__ s4, const float* __restrict__ s5,
                                const float* __restrict__ s6, const float* __restrict__ s7,
                                const float* __restrict__ s8, float* __restrict__ wt)
{
    const float* srcs[TSEG] = {s0, s1, s2, s3, s4, s5, s6, s7, s8};
    const int Ks[TSEG] = {128, 1280, 8, 64, 64, 64, 128, 128, 128};
    const int Ns[TSEG] = {128, 128, 64, 64, 64, 384, 128, 128, 128};
    const int dsts[TSEG] = {WUP_T, WSK_T, W1_T, W2_T, W3_T, W4_T, WL0_T, WL1_T, WL2_T};
    const int bases[TSEG] = {0, 16384, 180224, 180736, 184832, 188928,
                             213504, 229888, 246272};
    const int total = 262656;
    for (int i = blockIdx.x * blockDim.x + threadIdx.x; i < total;
         i += gridDim.x * blockDim.x) {
        int seg = 0;
#pragma unroll
        for (int s = 1; s < TSEG; s++)
            if (i >= bases[s]) seg = s;
        int local = i - bases[seg];
        int N = Ns[seg];
        int k = local / N;
        int c = local - k * N;
        wt[dsts[seg] + (size_t)c * Ks[seg] + k] = __ldg(&srcs[seg][local]);
    }
}

// ---------------- merge: tmp per-l coalesced -> out [n][c*9+jm] -------------
#define MPAD 132
__global__ void merge_k(const float* __restrict__ tmp, float* __restrict__ out)
{
    int n = blockIdx.x;
    int z = blockIdx.y;
    const float* t = tmp + (size_t)z * ZSZ;
    float* o = out + (size_t)z * NN * MID + (size_t)n * MID;
    __shared__ float s[9 * MPAD];
    int c = threadIdx.x;    // 128
    s[0 * MPAD + c] = t[L0OFF + (size_t)n * CC + c];
#pragma unroll
    for (int m = 0; m < 3; m++)
        s[(1 + m) * MPAD + c] = t[L1OFF + ((size_t)n * 3 + m) * CC + c];
#pragma unroll
    for (int m = 0; m < 5; m++)
        s[(4 + m) * MPAD + c] = t[L2OFF + ((size_t)n * 5 + m) * CC + c];
    __syncthreads();
#pragma unroll
    for (int it = 0; it < 9; it++) {
        int i = it * 128 + c;
        int cc = i / 9;
        int jm = i - cc * 9;
        o[i] = s[jm * MPAD + cc];
    }
}

// ---------------- y[n, u*A+v] = feats[n,u] * attrs[n,v] ---------------------
__global__ void yprep_k(const float* __restrict__ feats,
                        const float* __restrict__ attrs,
                        float* __restrict__ y)
{
    int n = blockIdx.x;
    __shared__ float sf[CC];
    __shared__ float sa[AA];
    if (threadIdx.x < CC) sf[threadIdx.x] = feats[(size_t)n * CC + threadIdx.x];
    if (threadIdx.x < AA) sa[threadIdx.x] = attrs[(size_t)n * AA + threadIdx.x];
    __syncthreads();
    for (int i = threadIdx.x; i < CC * AA; i += blockDim.x)
        y[(size_t)n * (CC * AA) + i] = sf[i / AA] * sa[i % AA];
}

// ---------------- CSR build -------------------------------------------------
__global__ void zero_deg_k(int* deg, int n)
{
    int i = blockIdx.x * blockDim.x + threadIdx.x;
    if (i < n) deg[i] = 0;
}
__global__ void count_deg_k(const int* __restrict__ recv, int* deg, int e)
{
    int i = blockIdx.x * blockDim.x + threadIdx.x;
    if (i < e) atomicAdd(&deg[recv[i]], 1);
}
__global__ void scan_k(const int* __restrict__ deg, int* off, int* pos, int n)
{
    __shared__ int wsum[32];
    __shared__ int carry_s;
    const int tid = threadIdx.x;
    const int lane = tid & 31;
    const int w = tid >> 5;
    if (tid == 0) carry_s = 0;
    __syncthreads();
    for (int base = 0; base < n; base += 1024) {
        int i = base + tid;
        int v = (i < n) ? deg[i] : 0;
        int x = v;
#pragma unroll
        for (int st = 1; st < 32; st <<= 1) {
            int t = __shfl_up_sync(0xFFFFFFFF, x, st);
            if (lane >= st) x += t;
        }
        if (lane == 31) wsum[w] = x;
        __syncthreads();
        if (w == 0) {
            int ws = (lane < 32) ? wsum[lane] : 0;
#pragma unroll
            for (int st = 1; st < 32; st <<= 1) {
                int t = __shfl_up_sync(0xFFFFFFFF, ws, st);
                if (lane >= st) ws += t;
            }
            wsum[lane] = ws;
        }
        __syncthreads();
        int incl = x + (w > 0 ? wsum[w - 1] : 0) + carry_s;
        int excl = incl - v;
        if (i < n) { off[i] = excl; pos[i] = excl; }
        __syncthreads();
        if (tid == 1023) carry_s = incl;
        __syncthreads();
    }
    if (threadIdx.x == 0) off[n] = carry_s;
}
__global__ void fill_eid_k(const int* __restrict__ recv, int* pos, int* eid, int e)
{
    int i = blockIdx.x * blockDim.x + threadIdx.x;
    if (i < e) {
        int p = atomicAdd(&pos[recv[i]], 1);
        eid[p] = i;
    }
}

// ---------------- gather: TP + segment sum (per receiver node) --------------
__global__ void gather_k(const float* __restrict__ h,
                         const float* __restrict__ tpw,
                         const float* __restrict__ yr,
                         const float* __restrict__ yi,
                         const int* __restrict__ senders,
                         const int* __restrict__ off,
                         const int* __restrict__ eid,
                         float* __restrict__ msg)
{
    int n = blockIdx.x;
    int c = threadIdx.x;   // 128 threads, one per channel
    float ar[9], ai[9];
#pragma unroll
    for (int j = 0; j < 9; j++) { ar[j] = 0.f; ai[j] = 0.f; }

    int e0 = __ldg(&off[n]);
    int e1 = __ldg(&off[n + 1]);
    for (int p = e0; p < e1; p++) {
        int e = __ldg(&eid[p]);
        int s = __ldg(&senders[e]);
        float hc = h[(size_t)s * CC + c];
        const float* tw = tpw + (size_t)e * 384;
        float xw0 = hc * tw[c];
        float xw1 = hc * tw[128 + c];
        float xw2 = hc * tw[256 + c];
        const float* er = yr + (size_t)e * 9;
        const float* ei = yi + (size_t)e * 9;
        ar[0] += xw0 * __ldg(&er[0]);
        ai[0] += xw0 * __ldg(&ei[0]);
#pragma unroll
        for (int m = 0; m < 3; m++) {
            ar[1 + m] += xw1 * __ldg(&er[1 + m]);
            ai[1 + m] += xw1 * __ldg(&ei[1 + m]);
        }
#pragma unroll
        for (int m = 0; m < 5; m++) {
            ar[4 + m] += xw2 * __ldg(&er[4 + m]);
            ai[4 + m] += xw2 * __ldg(&ei[4 + m]);
        }
    }

    float* mzr = msg;
    float* mzi = msg + ZSZ;
    mzr[L0OFF + (size_t)n * CC + c] = ar[0];
    mzi[L0OFF + (size_t)n * CC + c] = ai[0];
#pragma unroll
    for (int m = 0; m < 3; m++) {
        mzr[L1OFF + ((size_t)n * 3 + m) * CC + c] = ar[1 + m];
        mzi[L1OFF + ((size_t)n * 3 + m) * CC + c] = ai[1 + m];
    }
#pragma unroll
    for (int m = 0; m < 5; m++) {
        mzr[L2OFF + ((size_t)n * 5 + m) * CC + c] = ar[4 + m];
        mzi[L2OFF + ((size_t)n * 5 + m) * CC + c] = ai[4 + m];
    }
}

// ---------------- launch ----------------------------------------------------
static inline float* symf(const void* sym)
{
    void* p = nullptr;
    cudaGetSymbolAddress(&p, sym);
    return (float*)p;
}
static inline int* symi(const void* sym)
{
    void* p = nullptr;
    cudaGetSymbolAddress(&p, sym);
    return (int*)p;
}

static inline void tc_gemm(const float* A, int lda, const float* Bt, float* C,
                           int ldcr, int M, int Ncols, int K, int act)
{
    dim3 grid(Ncols / 64, (M + 127) / 128);
    tc_gemm_k<<<grid, 256, S_TOT>>>(A, lda, Bt, C, ldcr, M, K, act);
}

extern "C" void kernel_launch(void* const* d_in, const int* in_sizes, int n_in,
                              void* d_out, int out_size)
{
    const float* node_attrs = (const float*)d_in[0];
    const float* node_feats = (const float*)d_in[1];
    const float* yr         = (const float*)d_in[2];
    const float* yi         = (const float*)d_in[3];
    const float* edge_feats = (const float*)d_in[4];
    const int*   edge_index = (const int*)d_in[5];
    const float* W_up   = (const float*)d_in[6];
    const float* W_skip = (const float*)d_in[7];
    const float* W1     = (const float*)d_in[8];
    const float* W2     = (const float*)d_in[9];
    const float* W3     = (const float*)d_in[10];
    const float* W4     = (const float*)d_in[11];
    const float* Wl[3]  = { (const float*)d_in[12], (const float*)d_in[13],
                            (const float*)d_in[14] };
    float* out = (float*)d_out;

    static int smem_set = 0;
    if (!smem_set) {
        cudaFuncSetAttribute(tc_gemm_k,
                             cudaFuncAttributeMaxDynamicSharedMemorySize, S_TOT);
        smem_set = 1;
    }

    float* hh  = symf(g_h);
    float* yy  = symf(g_y);
    float* ta  = symf(g_ta);
    float* tb  = symf(g_tb);
    float* tpw = symf(g_tpw);
    float* msg = symf(g_msg);
    float* tmp = symf(g_tmp);
    float* wt  = symf(g_wt);
    int* deg = symi(g_deg);
    int* off = symi(g_off);
    int* pos = symi(g_pos);
    int* eid = symi(g_eid);

    const int* recv = edge_index + EE;
    const int* send = edge_index;

    // 0: all weight transposes fused into one launch
    transpose_all_k<<<1026, 256>>>(W_up, W_skip, W1, W2, W3, W4,
                                   Wl[0], Wl[1], Wl[2], wt);
    // 1: h = node_feats @ W_up
    tc_gemm(node_feats, CC, wt + WUP_T, hh, CC, NN, CC, CC, 0);
    // 2: y = outer(feats, attrs)
    yprep_k<<<NN, 256>>>(node_feats, node_attrs, yy);
    // 3: sc = y @ W_skip
    tc_gemm(yy, CC * AA, wt + WSK_T, out + SC_OFF, CC, NN, CC, CC * AA, 0);
    // 4-7: edge MLP
    tc_gemm(edge_feats, FF, wt + W1_T, ta, 64, EE, 64, FF, 1);
    tc_gemm(ta, 64, wt + W2_T, tb, 64, EE, 64, 64, 1);
    tc_gemm(tb, 64, wt + W3_T, ta, 64, EE, 64, 64, 1);
    tc_gemm(ta, 64, wt + W4_T, tpw, 384, EE, 384, 64, 0);
    // receiver CSR
    zero_deg_k<<<(NN + 255) / 256, 256>>>(deg, NN);
    count_deg_k<<<(EE + 255) / 256, 256>>>(recv, deg, EE);
    scan_k<<<1, 1024>>>(deg, off, pos, NN);
    fill_eid_k<<<(EE + 255) / 256, 256>>>(recv, pos, eid, EE);
    // tensor product + segment sum
    gather_k<<<NN, 128>>>(hh, tpw, yr, yi, send, off, eid, msg);
    // fused per-l channel-mixing linears -> coalesced tmp
    static const int ldim[3] = {1, 3, 5};
    static const int loff[3] = {L0OFF, L1OFF, L2OFF};
    for (int z = 0; z < 2; z++) {
        for (int l = 0; l < 3; l++) {
            int d = ldim[l];
            const float* Am = msg + (size_t)z * ZSZ + loff[l];
            float* Cm = tmp + (size_t)z * ZSZ + loff[l];
            tc_gemm(Am, CC, wt + (l == 0 ? WL0_T : l == 1 ? WL1_T : WL2_T),
                    Cm, CC, NN * d, CC, CC, 0);
        }
    }
    // merge tmp -> out (coalesced both sides)
    merge_k<<<dim3(NN, 2), 128>>>(tmp, out);
}

// round 10
// speedup vs baseline: 2.1318x; 1.2094x over previous
#include <cuda_runtime.h>
#include <cuda_bf16.h>
#include <math.h>
#include <stdint.h>

// Problem constants (fixed shapes)
#define NN 10000
#define EE 128000
#define CC 128
#define AA 10
#define FF 8
#define MID 1152                       // C * 9
#define SC_OFF (2 * NN * MID)

// msg internal layout per z: [ l0: N*1*C | l1: N*3*C | l2: N*5*C ]
#define ZSZ   (NN * 9 * CC)
#define L0OFF 0
#define L1OFF (NN * CC)
#define L2OFF (4 * NN * CC)

typedef __nv_bfloat16 bf16;

// ---------------- scratch (static device globals) ---------------------------
__device__ __align__(128) float g_h[NN * CC];              // fp32 (gather input)
__device__ __align__(128) float g_tpw[(size_t)EE * 384];   // fp32 (gather input)
__device__ __align__(128) float g_tmp[2 * ZSZ];            // irreps GEMM output
// bf16 hi/lo operand pairs
__device__ __align__(128) bf16 g_nfh[NN * CC];
__device__ __align__(128) bf16 g_nfl[NN * CC];
__device__ __align__(128) bf16 g_efh[EE * 64];
__device__ __align__(128) bf16 g_efl[EE * 64];
__device__ __align__(128) bf16 g_yh[NN * CC * AA];
__device__ __align__(128) bf16 g_yl[NN * CC * AA];
__device__ __align__(128) bf16 g_tah[EE * 64];
__device__ __align__(128) bf16 g_tal[EE * 64];
__device__ __align__(128) bf16 g_tbh[EE * 64];
__device__ __align__(128) bf16 g_tbl[EE * 64];
__device__ __align__(128) bf16 g_msgh[2 * ZSZ];
__device__ __align__(128) bf16 g_msgl[2 * ZSZ];
__device__ __align__(128) bf16 g_wth[266240];
__device__ __align__(128) bf16 g_wtl[266240];
__device__ int   g_deg[NN + 8];
__device__ int   g_off[NN + 8];
__device__ int   g_pos[NN + 8];
__device__ int   g_eid[EE];

// transposed-weight offsets inside g_wt (all K padded to multiples of 64)
#define WUP_T 0
#define WSK_T 16384
#define W1_T  180224
#define W2_T  184320
#define W3_T  188416
#define W4_T  192512
#define WL0_T 217088
#define WL1_T 233472
#define WL2_T 249856
#define WT_TOTAL 266240

// ---------------- helpers ---------------------------------------------------
__device__ __forceinline__ uint32_t smem_to_u32(const void* p) {
    uint32_t a;
    asm("{ .reg .u64 t; cvta.to.shared.u64 t, %1; cvt.u32.u64 %0, t; }"
        : "=r"(a) : "l"(p));
    return a;
}

__device__ __forceinline__ void ldm_x4(uint32_t addr, uint32_t* r) {
    asm volatile("ldmatrix.sync.aligned.m8n8.x4.shared.b16 {%0,%1,%2,%3}, [%4];"
                 : "=r"(r[0]), "=r"(r[1]), "=r"(r[2]), "=r"(r[3]) : "r"(addr));
}

__device__ __forceinline__ void mma16816(float* d, const uint32_t* a,
                                         const uint32_t* b) {
    asm volatile("mma.sync.aligned.m16n8k16.row.col.f32.bf16.bf16.f32 "
                 "{%0,%1,%2,%3}, {%4,%5,%6,%7}, {%8,%9}, {%0,%1,%2,%3};"
                 : "+f"(d[0]), "+f"(d[1]), "+f"(d[2]), "+f"(d[3])
                 : "r"(a[0]), "r"(a[1]), "r"(a[2]), "r"(a[3]),
                   "r"(b[0]), "r"(b[1]));
}

#define CP16(dst, src) \
    asm volatile("cp.async.cg.shared.global [%0], [%1], 16;" \
                 :: "r"(dst), "l"(src) : "memory")
#define CP_COMMIT() asm volatile("cp.async.commit_group;" ::: "memory")
#define CP_WAIT0()  asm volatile("cp.async.wait_group 0;" ::: "memory")
#define CP_WAIT1()  asm volatile("cp.async.wait_group 1;" ::: "memory")

__device__ __forceinline__ void split1(float v, bf16& hi, bf16& lo)
{
    hi = __float2bfloat16_rn(v);
    lo = __float2bfloat16_rn(v - __bfloat162float(hi));
}

// ---------------- mma.sync bf16 pre-split GEMM, cp.async pipelined ----------
// C = act( A[MxK] @ Bt[Ncols x K]^T ).  A,B given as bf16 hi/lo pairs, lda=K.
// Block tile 128x64, K-chunk 64, 8 warps (4m x 2n), warp tile 32x32.
// Output: fp32 to Cf (if non-null) and/or bf16 hi/lo to Oh/Ol.
#define ROWB 144
#define SA_H 0
#define SA_L (128 * ROWB)
#define SB_H (2 * 128 * ROWB)
#define SB_L (2 * 128 * ROWB + 64 * ROWB)
#define SSTG (2 * 128 * ROWB + 2 * 64 * ROWB)   // 55296 per stage
#define S_TOT (2 * SSTG)                         // 110592

__global__ __launch_bounds__(256)
void tc_gemm_k(const bf16* __restrict__ Ah, const bf16* __restrict__ Al,
               const bf16* __restrict__ Bh, const bf16* __restrict__ Bl,
               float* __restrict__ Cf, bf16* __restrict__ Oh,
               bf16* __restrict__ Ol, int ldcr,
               int M, int K, int act)
{
    extern __shared__ char smem[];
    const uint32_t sb = smem_to_u32(smem);
    const int tid = threadIdx.x;
    const int lane = tid & 31;
    const int wid = tid >> 5;
    const int wm = (wid & 3) * 32;
    const int wn = (wid >> 2) * 32;
    const int bm = blockIdx.y * 128;
    const int bn = blockIdx.x * 64;
    const int nchunks = K >> 6;          // K is a multiple of 64

    float acc[2][4][4];
#pragma unroll
    for (int i = 0; i < 2; i++)
#pragma unroll
        for (int j = 0; j < 4; j++)
#pragma unroll
            for (int q = 0; q < 4; q++) acc[i][j][q] = 0.f;

    // staging assignment (per chunk): A 2048 16B-units, B 1024 16B-units
    // A: unit = tid + li*256 ; buf = unit>>10 ; idx = unit&1023 ; r=idx>>3 ; c=idx&7
    // B: unit = tid + li*256 ; buf = unit>>9  ; idx = unit&511  ; r=idx>>3 ; c=idx&7
    auto stage = [&](int ch) {
        const int k0 = ch << 6;
        const uint32_t stg = sb + (uint32_t)((ch & 1) * SSTG);
#pragma unroll
        for (int li = 0; li < 8; li++) {
            int u = tid + li * 256;
            int buf = u >> 10;
            int idx = u & 1023;
            int r = idx >> 3;
            int c = idx & 7;
            int gr = bm + r;
            if (gr >= M) gr = M - 1;      // clamp: garbage rows are discarded
            const bf16* src = (buf ? Al : Ah) + (size_t)gr * K + k0 + c * 8;
            uint32_t dst = stg + (buf ? SA_L : SA_H) + r * ROWB + c * 16;
            CP16(dst, src);
        }
#pragma unroll
        for (int li = 0; li < 4; li++) {
            int u = tid + li * 256;
            int buf = u >> 9;
            int idx = u & 511;
            int r = idx >> 3;
            int c = idx & 7;
            const bf16* src = (buf ? Bl : Bh) + (size_t)(bn + r) * K + k0 + c * 8;
            uint32_t dst = stg + (buf ? SB_L : SB_H) + r * ROWB + c * 16;
            CP16(dst, src);
        }
        CP_COMMIT();
    };

    const uint32_t aRow = wm + (lane & 15);
    const uint32_t aKp = (lane >> 4) * 8;
    const uint32_t aOff0 = aRow * ROWB + aKp * 2;
    const uint32_t aOff1 = (aRow + 16) * ROWB + aKp * 2;
    const uint32_t bRow = (lane & 7) + ((lane >> 4) * 8);
    const uint32_t bKp = ((lane >> 3) & 1) * 8;
    const uint32_t bOff0 = (wn + bRow) * ROWB + bKp * 2;
    const uint32_t bOff1 = (wn + 16 + bRow) * ROWB + bKp * 2;

    stage(0);

    for (int ch = 0; ch < nchunks; ch++) {
        if (ch + 1 < nchunks) {
            stage(ch + 1);
            CP_WAIT1();
        } else {
            CP_WAIT0();
        }
        __syncthreads();
        const uint32_t stg = sb + (uint32_t)((ch & 1) * SSTG);

#pragma unroll
        for (int ks = 0; ks < 4; ks++) {
            const uint32_t k2 = (uint32_t)(ks * 32);
            uint32_t a0[4], a1[4], b0[4], b1[4], bl0[4], bl1[4];
            ldm_x4(stg + SA_H + aOff0 + k2, a0);
            ldm_x4(stg + SA_H + aOff1 + k2, a1);
            ldm_x4(stg + SB_H + bOff0 + k2, b0);
            ldm_x4(stg + SB_H + bOff1 + k2, b1);
            mma16816(acc[0][0], a0, b0 + 0);
            mma16816(acc[0][1], a0, b0 + 2);
            mma16816(acc[0][2], a0, b1 + 0);
            mma16816(acc[0][3], a0, b1 + 2);
            mma16816(acc[1][0], a1, b0 + 0);
            mma16816(acc[1][1], a1, b0 + 2);
            mma16816(acc[1][2], a1, b1 + 0);
            mma16816(acc[1][3], a1, b1 + 2);
            ldm_x4(stg + SB_L + bOff0 + k2, bl0);
            ldm_x4(stg + SB_L + bOff1 + k2, bl1);
            mma16816(acc[0][0], a0, bl0 + 0);
            mma16816(acc[0][1], a0, bl0 + 2);
            mma16816(acc[0][2], a0, bl1 + 0);
            mma16816(acc[0][3], a0, bl1 + 2);
            mma16816(acc[1][0], a1, bl0 + 0);
            mma16816(acc[1][1], a1, bl0 + 2);
            mma16816(acc[1][2], a1, bl1 + 0);
            mma16816(acc[1][3], a1, bl1 + 2);
            ldm_x4(stg + SA_L + aOff0 + k2, a0);
            ldm_x4(stg + SA_L + aOff1 + k2, a1);
            mma16816(acc[0][0], a0, b0 + 0);
            mma16816(acc[0][1], a0, b0 + 2);
            mma16816(acc[0][2], a0, b1 + 0);
            mma16816(acc[0][3], a0, b1 + 2);
            mma16816(acc[1][0], a1, b0 + 0);
            mma16816(acc[1][1], a1, b0 + 2);
            mma16816(acc[1][2], a1, b1 + 0);
            mma16816(acc[1][3], a1, b1 + 2);
        }
        __syncthreads();
    }

    // ---- epilogue ----
#pragma unroll
    for (int mt = 0; mt < 2; mt++) {
        int r0g = bm + wm + mt * 16 + (lane >> 2);
#pragma unroll
        for (int nt = 0; nt < 4; nt++) {
            int cg = bn + wn + nt * 8 + (lane & 3) * 2;
            float* d = acc[mt][nt];
#pragma unroll
            for (int half = 0; half < 2; half++) {
                int r = r0g + half * 8;
                if (r >= M) continue;
                float v0 = d[half * 2 + 0];
                float v1 = d[half * 2 + 1];
                if (act) {
                    v0 = v0 / (1.f + __expf(-v0));
                    v1 = v1 / (1.f + __expf(-v1));
                }
                size_t base = (size_t)r * ldcr + cg;
                if (Cf) {
                    Cf[base] = v0;
                    Cf[base + 1] = v1;
                }
                if (Oh) {
                    bf16 h0, l0, h1, l1;
                    split1(v0, h0, l0);
                    split1(v1, h1, l1);
                    Oh[base] = h0;
                    Ol[base] = l0;
                    Oh[base + 1] = h1;
                    Ol[base + 1] = l1;
                }
            }
        }
    }
}

// ---------------- fused weight transpose + bf16 split -----------------------
#define TSEG 9
__global__ void transpose_all_k(const float* __restrict__ s0, const float* __restrict__ s1,
                                const float* __restrict__ s2, const float* __restrict__ s3,
                                const float* __restrict__ s4, const float* __restrict__ s5,
                                const float* __restrict__ s6, const float* __restrict__ s7,
                                const float* __restrict__ s8,
                                bf16* __restrict__ wth, bf16* __restrict__ wtl)
{
    const float* srcs[TSEG] = {s0, s1, s2, s3, s4, s5, s6, s7, s8};
    const int Ksrc[TSEG] = {128, 1280, 8, 64, 64, 64, 128, 128, 128};
    const int Kdst[TSEG] = {128, 1280, 64, 64, 64, 64, 128, 128, 128};
    const int Ns[TSEG]   = {128, 128, 64, 64, 64, 384, 128, 128, 128};
    const int bases[TSEG] = {WUP_T, WSK_T, W1_T, W2_T, W3_T, W4_T,
                             WL0_T, WL1_T, WL2_T};
    for (int i = blockIdx.x * blockDim.x + threadIdx.x; i < WT_TOTAL;
         i += gridDim.x * blockDim.x) {
        int seg = 0;
#pragma unroll
        for (int s = 1; s < TSEG; s++)
            if (i >= bases[s]) seg = s;
        int local = i - bases[seg];
        int K = Kdst[seg];
        int c = local / K;
        int k = local - c * K;
        float v = (k < Ksrc[seg]) ? __ldg(&srcs[seg][(size_t)k * Ns[seg] + c]) : 0.f;
        bf16 hi, lo;
        split1(v, hi, lo);
        wth[i] = hi;
        wtl[i] = lo;
    }
}

// ---------------- fp32 -> bf16 hi/lo convert (with K padding) ---------------
__global__ void conv_split_k(const float* __restrict__ in, bf16* __restrict__ oh,
                             bf16* __restrict__ ol, int M, int Kin, int Kout)
{
    for (int i = blockIdx.x * blockDim.x + threadIdx.x; i < M * Kout;
         i += gridDim.x * blockDim.x) {
        int r = i / Kout;
        int k = i - r * Kout;
        float v = (k < Kin) ? __ldg(&in[(size_t)r * Kin + k]) : 0.f;
        bf16 hi, lo;
        split1(v, hi, lo);
        oh[i] = hi;
        ol[i] = lo;
    }
}

// ---------------- merge: tmp per-l coalesced -> out [n][c*9+jm] -------------
#define MPAD 132
__global__ void merge_k(const float* __restrict__ tmp, float* __restrict__ out)
{
    int n = blockIdx.x;
    int z = blockIdx.y;
    const float* t = tmp + (size_t)z * ZSZ;
    float* o = out + (size_t)z * NN * MID + (size_t)n * MID;
    __shared__ float s[9 * MPAD];
    int c = threadIdx.x;    // 128
    s[0 * MPAD + c] = t[L0OFF + (size_t)n * CC + c];
#pragma unroll
    for (int m = 0; m < 3; m++)
        s[(1 + m) * MPAD + c] = t[L1OFF + ((size_t)n * 3 + m) * CC + c];
#pragma unroll
    for (int m = 0; m < 5; m++)
        s[(4 + m) * MPAD + c] = t[L2OFF + ((size_t)n * 5 + m) * CC + c];
    __syncthreads();
#pragma unroll
    for (int it = 0; it < 9; it++) {
        int i = it * 128 + c;
        int cc = i / 9;
        int jm = i - cc * 9;
        o[i] = s[jm * MPAD + cc];
    }
}

// ---------------- y outer product, bf16 hi/lo output -------------------------
__global__ void yprep_k(const float* __restrict__ feats,
                        const float* __restrict__ attrs,
                        bf16* __restrict__ yh, bf16* __restrict__ yl)
{
    int n = blockIdx.x;
    __shared__ float sf[CC];
    __shared__ float sa[AA];
    if (threadIdx.x < CC) sf[threadIdx.x] = feats[(size_t)n * CC + threadIdx.x];
    if (threadIdx.x < AA) sa[threadIdx.x] = attrs[(size_t)n * AA + threadIdx.x];
    __syncthreads();
    for (int i = threadIdx.x; i < CC * AA; i += blockDim.x) {
        float v = sf[i / AA] * sa[i % AA];
        bf16 hi, lo;
        split1(v, hi, lo);
        yh[(size_t)n * (CC * AA) + i] = hi;
        yl[(size_t)n * (CC * AA) + i] = lo;
    }
}

// ---------------- CSR build -------------------------------------------------
__global__ void zero_deg_k(int* deg, int n)
{
    int i = blockIdx.x * blockDim.x + threadIdx.x;
    if (i < n) deg[i] = 0;
}
__global__ void count_deg_k(const int* __restrict__ recv, int* deg, int e)
{
    int i = blockIdx.x * blockDim.x + threadIdx.x;
    if (i < e) atomicAdd(&deg[recv[i]], 1);
}
__global__ void scan_k(const int* __restrict__ deg, int* off, int* pos, int n)
{
    __shared__ int wsum[32];
    __shared__ int carry_s;
    const int tid = threadIdx.x;
    const int lane = tid & 31;
    const int w = tid >> 5;
    if (tid == 0) carry_s = 0;
    __syncthreads();
    for (int base = 0; base < n; base += 1024) {
        int i = base + tid;
        int v = (i < n) ? deg[i] : 0;
        int x = v;
#pragma unroll
        for (int st = 1; st < 32; st <<= 1) {
            int t = __shfl_up_sync(0xFFFFFFFF, x, st);
            if (lane >= st) x += t;
        }
        if (lane == 31) wsum[w] = x;
        __syncthreads();
        if (w == 0) {
            int ws = (lane < 32) ? wsum[lane] : 0;
#pragma unroll
            for (int st = 1; st < 32; st <<= 1) {
                int t = __shfl_up_sync(0xFFFFFFFF, ws, st);
                if (lane >= st) ws += t;
            }
            wsum[lane] = ws;
        }
        __syncthreads();
        int incl = x + (w > 0 ? wsum[w - 1] : 0) + carry_s;
        int excl = incl - v;
        if (i < n) { off[i] = excl; pos[i] = excl; }
        __syncthreads();
        if (tid == 1023) carry_s = incl;
        __syncthreads();
    }
    if (threadIdx.x == 0) off[n] = carry_s;
}
__global__ void fill_eid_k(const int* __restrict__ recv, int* pos, int* eid, int e)
{
    int i = blockIdx.x * blockDim.x + threadIdx.x;
    if (i < e) {
        int p = atomicAdd(&pos[recv[i]], 1);
        eid[p] = i;
    }
}

// ---------------- gather: TP + segment sum, bf16 hi/lo msg output -----------
__global__ void gather_k(const float* __restrict__ h,
                         const float* __restrict__ tpw,
                         const float* __restrict__ yr,
                         const float* __restrict__ yi,
                         const int* __restrict__ senders,
                         const int* __restrict__ off,
                         const int* __restrict__ eid,
                         bf16* __restrict__ msgh, bf16* __restrict__ msgl)
{
    int n = blockIdx.x;
    int c = threadIdx.x;   // 128 threads, one per channel
    float ar[9], ai[9];
#pragma unroll
    for (int j = 0; j < 9; j++) { ar[j] = 0.f; ai[j] = 0.f; }

    int e0 = __ldg(&off[n]);
    int e1 = __ldg(&off[n + 1]);
    for (int p = e0; p < e1; p++) {
        int e = __ldg(&eid[p]);
        int s = __ldg(&senders[e]);
        float hc = h[(size_t)s * CC + c];
        const float* tw = tpw + (size_t)e * 384;
        float xw0 = hc * tw[c];
        float xw1 = hc * tw[128 + c];
        float xw2 = hc * tw[256 + c];
        const float* er = yr + (size_t)e * 9;
        const float* ei = yi + (size_t)e * 9;
        ar[0] += xw0 * __ldg(&er[0]);
        ai[0] += xw0 * __ldg(&ei[0]);
#pragma unroll
        for (int m = 0; m < 3; m++) {
            ar[1 + m] += xw1 * __ldg(&er[1 + m]);
            ai[1 + m] += xw1 * __ldg(&ei[1 + m]);
        }
#pragma unroll
        for (int m = 0; m < 5; m++) {
            ar[4 + m] += xw2 * __ldg(&er[4 + m]);
            ai[4 + m] += xw2 * __ldg(&ei[4 + m]);
        }
    }

    // per-l contiguous layout, split to bf16 hi/lo
#pragma unroll
    for (int z = 0; z < 2; z++) {
        const float* a = z ? ai : ar;
        bf16* mh = msgh + (size_t)z * ZSZ;
        bf16* ml = msgl + (size_t)z * ZSZ;
        bf16 hi, lo;
        split1(a[0], hi, lo);
        mh[L0OFF + (size_t)n * CC + c] = hi;
        ml[L0OFF + (size_t)n * CC + c] = lo;
#pragma unroll
        for (int m = 0; m < 3; m++) {
            split1(a[1 + m], hi, lo);
            mh[L1OFF + ((size_t)n * 3 + m) * CC + c] = hi;
            ml[L1OFF + ((size_t)n * 3 + m) * CC + c] = lo;
        }
#pragma unroll
        for (int m = 0; m < 5; m++) {
            split1(a[4 + m], hi, lo);
            mh[L2OFF + ((size_t)n * 5 + m) * CC + c] = hi;
            ml[L2OFF + ((size_t)n * 5 + m) * CC + c] = lo;
        }
    }
}

// ---------------- launch ----------------------------------------------------
static inline float* symf(const void* sym)
{
    void* p = nullptr;
    cudaGetSymbolAddress(&p, sym);
    return (float*)p;
}
static inline bf16* symb(const void* sym)
{
    void* p = nullptr;
    cudaGetSymbolAddress(&p, sym);
    return (bf16*)p;
}
static inline int* symi(const void* sym)
{
    void* p = nullptr;
    cudaGetSymbolAddress(&p, sym);
    return (int*)p;
}

static inline void tc_gemm(const bf16* Ah, const bf16* Al,
                           const bf16* Bh, const bf16* Bl,
                           float* Cf, bf16* Oh, bf16* Ol, int ldcr,
                           int M, int Ncols, int K, int act)
{
    dim3 grid(Ncols / 64, (M + 127) / 128);
    tc_gemm_k<<<grid, 256, S_TOT>>>(Ah, Al, Bh, Bl, Cf, Oh, Ol, ldcr, M, K, act);
}

extern "C" void kernel_launch(void* const* d_in, const int* in_sizes, int n_in,
                              void* d_out, int out_size)
{
    const float* node_attrs = (const float*)d_in[0];
    const float* node_feats = (const float*)d_in[1];
    const float* yr         = (const float*)d_in[2];
    const float* yi         = (const float*)d_in[3];
    const float* edge_feats = (const float*)d_in[4];
    const int*   edge_index = (const int*)d_in[5];
    const float* W_up   = (const float*)d_in[6];
    const float* W_skip = (const float*)d_in[7];
    const float* W1     = (const float*)d_in[8];
    const float* W2     = (const float*)d_in[9];
    const float* W3     = (const float*)d_in[10];
    const float* W4     = (const float*)d_in[11];
    const float* Wl[3]  = { (const float*)d_in[12], (const float*)d_in[13],
                            (const float*)d_in[14] };
    float* out = (float*)d_out;

    static int smem_set = 0;
    if (!smem_set) {
        cudaFuncSetAttribute(tc_gemm_k,
                             cudaFuncAttributeMaxDynamicSharedMemorySize, S_TOT);
        smem_set = 1;
    }

    float* hh   = symf(g_h);
    float* tpw  = symf(g_tpw);
    float* tmp  = symf(g_tmp);
    bf16* nfh = symb(g_nfh); bf16* nfl = symb(g_nfl);
    bf16* efh = symb(g_efh); bf16* efl = symb(g_efl);
    bf16* yh  = symb(g_yh);  bf16* yl  = symb(g_yl);
    bf16* tah = symb(g_tah); bf16* tal = symb(g_tal);
    bf16* tbh = symb(g_tbh); bf16* tbl = symb(g_tbl);
    bf16* msgh = symb(g_msgh); bf16* msgl = symb(g_msgl);
    bf16* wth = symb(g_wth); bf16* wtl = symb(g_wtl);
    int* deg = symi(g_deg);
    int* off = symi(g_off);
    int* pos = symi(g_pos);
    int* eid = symi(g_eid);

    const int* recv = edge_index + EE;
    const int* send = edge_index;

    // prep: weight transpose+split, input conversions (all independent)
    transpose_all_k<<<1040, 256>>>(W_up, W_skip, W1, W2, W3, W4,
                                   Wl[0], Wl[1], Wl[2], wth, wtl);
    conv_split_k<<<1024, 256>>>(node_feats, nfh, nfl, NN, CC, CC);
    conv_split_k<<<2048, 256>>>(edge_feats, efh, efl, EE, FF, 64);
    yprep_k<<<NN, 256>>>(node_feats, node_attrs, yh, yl);
    // CSR (independent of GEMMs)
    zero_deg_k<<<(NN + 255) / 256, 256>>>(deg, NN);
    count_deg_k<<<(EE + 255) / 256, 256>>>(recv, deg, EE);
    scan_k<<<1, 1024>>>(deg, off, pos, NN);
    fill_eid_k<<<(EE + 255) / 256, 256>>>(recv, pos, eid, EE);

    // h = node_feats @ W_up  (fp32 out, gather input)
    tc_gemm(nfh, nfl, wth + WUP_T, wtl + WUP_T, hh, nullptr, nullptr, CC,
            NN, CC, CC, 0);
    // sc = y @ W_skip  (fp32 out, final)
    tc_gemm(yh, yl, wth + WSK_T, wtl + WSK_T, out + SC_OFF, nullptr, nullptr, CC,
            NN, CC, CC * AA, 0);
    // edge MLP (bf16 hi/lo chain)
    tc_gemm(efh, efl, wth + W1_T, wtl + W1_T, nullptr, tah, tal, 64,
            EE, 64, 64, 1);
    tc_gemm(tah, tal, wth + W2_T, wtl + W2_T, nullptr, tbh, tbl, 64,
            EE, 64, 64, 1);
    tc_gemm(tbh, tbl, wth + W3_T, wtl + W3_T, nullptr, tah, tal, 64,
            EE, 64, 64, 1);
    tc_gemm(tah, tal, wth + W4_T, wtl + W4_T, tpw, nullptr, nullptr, 384,
            EE, 384, 64, 0);
    // tensor product + segment sum (writes bf16 hi/lo msg)
    gather_k<<<NN, 128>>>(hh, tpw, yr, yi, send, off, eid, msgh, msgl);
    // fused per-l channel-mixing linears -> coalesced tmp (fp32)
    static const int ldim[3] = {1, 3, 5};
    static const int loff[3] = {L0OFF, L1OFF, L2OFF};
    static const int wlo[3] = {WL0_T, WL1_T, WL2_T};
    for (int z = 0; z < 2; z++) {
        for (int l = 0; l < 3; l++) {
            int d = ldim[l];
            const bf16* Amh = msgh + (size_t)z * ZSZ + loff[l];
            const bf16* Aml = msgl + (size_t)z * ZSZ + loff[l];
            float* Cm = tmp + (size_t)z * ZSZ + loff[l];
            tc_gemm(Amh, Aml, wth + wlo[l], wtl + wlo[l], Cm, nullptr, nullptr,
                    CC, NN * d, CC, CC, 0);
        }
    }
    // merge tmp -> out (coalesced both sides)
    merge_k<<<dim3(NN, 2), 128>>>(tmp, out);
}